// round 12
// baseline (speedup 1.0000x reference)
#include <cuda_runtime.h>
#include <cuda_bf16.h>
#include <cstring>
#include <cstdint>

// Shapes
#define BB 32
#define TT 64
#define NN 300
#define DD 128
#define ND (NN*DD)          // 38400
#define BT (BB*TT)          // 2048

// Scratch (static __device__ — no allocation allowed)
__device__ float    g_Q[BB*TT*NN];      // [b,t,n]
__device__ float    g_K[BB*TT*DD];      // [b,t,d]
__device__ float    g_S[BB*TT*TT];      // scores [b,q,k]
__device__ uint32_t g_Ah[BB*TT*32];     // att^T bf16x2 hi: [b][a][t/2]
__device__ uint32_t g_Al[BB*TT*32];     // att^T bf16x2 lo: [b][a][t/2]

__device__ __forceinline__ float bf16_round(float v) {
    return __bfloat162float(__float2bfloat16_rn(v));
}
// pack two floats as bf16x2; 'lo' goes to bits [15:0] (lower k index)
__device__ __forceinline__ uint32_t pack_bf16x2(float lo, float hi) {
    uint32_t r;
    asm("cvt.rn.bf16x2.f32 %0, %1, %2;" : "=r"(r) : "f"(hi), "f"(lo));
    return r;
}
__device__ __forceinline__ void cp_async16(uint32_t dst_smem, const void* src) {
    asm volatile("cp.async.cg.shared.global [%0], [%1], 16;"
                 :: "r"(dst_smem), "l"(src));
}

// ---------------------------------------------------------------------------
// Kernel 1 (FUSED, single pass over src) — round-6 version, unroll 8 for MLP:
//   Q[bt,n] = dot(src[bt,n,:], wt1);  K[bt,d] = sum_n wt3[n]*src[bt,n,d]
// ---------------------------------------------------------------------------
#define SP_STRIDE 33

__global__ void __launch_bounds__(256)
qk_kernel(const float* __restrict__ src,
          const float* __restrict__ wt1,
          const float* __restrict__ wt3) {
    const int bt  = blockIdx.x;
    const int tid = threadIdx.x;
    const float* base = src + (size_t)bt * ND;

    __shared__ float  sw3[NN];
    __shared__ float  sP[NN * SP_STRIDE];
    __shared__ float4 sKred[8][32];

    for (int i = tid; i < NN; i += 256) sw3[i] = wt3[i];
    __syncthreads();

    const int warp = tid >> 5, lane = tid & 31;
    const float4 w1v = reinterpret_cast<const float4*>(wt1)[lane];
    float4 kacc = make_float4(0.f, 0.f, 0.f, 0.f);

    #pragma unroll 8
    for (int n = warp; n < NN; n += 8) {
        const float4 v = reinterpret_cast<const float4*>(base + n * DD)[lane];
        const float w3n = sw3[n];
        kacc.x += w3n * v.x; kacc.y += w3n * v.y;
        kacc.z += w3n * v.z; kacc.w += w3n * v.w;
        sP[n * SP_STRIDE + lane] =
            v.x * w1v.x + v.y * w1v.y + v.z * w1v.z + v.w * w1v.w;
    }

    sKred[warp][lane] = kacc;
    __syncthreads();

    for (int n = tid; n < NN; n += 256) {
        const float* row = sP + n * SP_STRIDE;
        float s = 0.f;
        #pragma unroll
        for (int j = 0; j < 32; ++j) s += row[j];
        g_Q[bt * NN + n] = s;
    }

    if (tid < 128) {
        const int l = tid >> 2, comp = tid & 3;
        float s = 0.f;
        #pragma unroll
        for (int w = 0; w < 8; ++w)
            s += reinterpret_cast<const float*>(&sKred[w][l])[comp];
        g_K[bt * DD + tid] = s;
    }
}

// ---------------------------------------------------------------------------
// Kernel 2 (FUSED m+scores): per (b, 8-q tile) — 256 CTAs, warp = 1 q row.
//   M[q,d] = sum_n Q[b,q,n]*wt2[n,d]  (smem)   then
//   scores[b,q,k] = sum_d M[q,d]*K[b,k,d]
// ---------------------------------------------------------------------------
__global__ void __launch_bounds__(256)
mscores_kernel(const float* __restrict__ wt2) {
    const int b = blockIdx.x, qt = blockIdx.y;   // qt in [0,8)
    const int tid = threadIdx.x;
    const int warp = tid >> 5, lane = tid & 31;

    __shared__ float sQ[8 * NN];       // 9.6 KB
    __shared__ float sM[8 * DD];       // 4 KB
    __shared__ float sK[TT * 129];     // 33 KB

    for (int i = tid; i < 8 * NN; i += 256)
        sQ[i] = g_Q[(b * TT + qt * 8) * NN + i];
    for (int i = tid; i < TT * DD; i += 256) {
        const int k = i >> 7, d = i & 127;
        sK[k * 129 + d] = g_K[(b * TT + k) * DD + d];
    }
    __syncthreads();

    // --- M phase: warp -> 1 q row; lane -> 4 d columns ---
    {
        const int q = warp;
        float acc[4] = {0.f, 0.f, 0.f, 0.f};
        #pragma unroll 4
        for (int n = 0; n < NN; ++n) {
            const float qv = sQ[q * NN + n];
            const float* w2 = wt2 + n * DD;
            #pragma unroll
            for (int j = 0; j < 4; ++j)
                acc[j] += qv * w2[lane + 32 * j];
        }
        #pragma unroll
        for (int j = 0; j < 4; ++j)
            sM[q * DD + lane + 32 * j] = acc[j];
    }
    __syncthreads();

    // --- scores phase: 512 outputs, 2 per thread ---
    #pragma unroll
    for (int pi = 0; pi < 2; ++pi) {
        const int p = pi * 256 + tid;
        const int q = p >> 6, k = p & 63;
        float acc = 0.f;
        #pragma unroll 8
        for (int d = 0; d < DD; ++d)
            acc += sM[q * DD + d] * sK[k * 129 + d];
        g_S[(b * TT + qt * 8 + q) * TT + k] = acc;
    }
}

// ---------------------------------------------------------------------------
// Kernel 3: softmax over BATCH axis + transpose + bf16 hi/lo pre-pack
// (round-6 exact; NO identity fold — mix adds the residual in fp32).
// ---------------------------------------------------------------------------
__global__ void __launch_bounds__(256)
softmax_kernel() {
    const int warp = threadIdx.x >> 5, lane = threadIdx.x & 31;
    const int w  = blockIdx.x * 8 + warp;
    const int a  = w >> 5, tp = w & 31;

    const float x0 = g_S[lane * (TT * TT) + (2 * tp) * TT + a];
    const float x1 = g_S[lane * (TT * TT) + (2 * tp + 1) * TT + a];
    float m0 = x0, m1 = x1;
    #pragma unroll
    for (int off = 16; off > 0; off >>= 1) {
        m0 = fmaxf(m0, __shfl_xor_sync(0xffffffffu, m0, off));
        m1 = fmaxf(m1, __shfl_xor_sync(0xffffffffu, m1, off));
    }
    const float e0 = __expf(x0 - m0), e1 = __expf(x1 - m1);
    float s0 = e0, s1 = e1;
    #pragma unroll
    for (int off = 16; off > 0; off >>= 1) {
        s0 += __shfl_xor_sync(0xffffffffu, s0, off);
        s1 += __shfl_xor_sync(0xffffffffu, s1, off);
    }
    const float v0 = e0 / s0, v1 = e1 / s1;
    const float h0 = bf16_round(v0), h1 = bf16_round(v1);
    g_Ah[lane * 2048 + a * 32 + tp] = pack_bf16x2(h0, h1);
    g_Al[lane * 2048 + a * 32 + tp] = pack_bf16x2(v0 - h0, v1 - h1);
}

// ---------------------------------------------------------------------------
// Kernel 4 (TENSOR) — round-6 EXACT (proven best: 131.9us):
// mixed[a,c] = sum_t att^T[a,t]*src[t,c]; out = mixed + src.
// bf16-split MMA; 64x256 tile; 2 CTAs/SM; register-lean mainloop.
// ---------------------------------------------------------------------------
#define SS_STRIDE 260   // floats; conflict-free
#define SA_STRIDE 36    // uint32; conflict-free
#define MIX_SMEM_BYTES (TT*SS_STRIDE*4 + 2*TT*SA_STRIDE*4)   // 84992

__device__ __forceinline__ void mma_bf16(float c[4],
                                         uint32_t a0, uint32_t a1,
                                         uint32_t a2, uint32_t a3,
                                         uint32_t b0, uint32_t b1) {
    asm volatile(
        "mma.sync.aligned.m16n8k16.row.col.f32.bf16.bf16.f32 "
        "{%0,%1,%2,%3}, {%4,%5,%6,%7}, {%8,%9}, {%0,%1,%2,%3};"
        : "+f"(c[0]), "+f"(c[1]), "+f"(c[2]), "+f"(c[3])
        : "r"(a0), "r"(a1), "r"(a2), "r"(a3), "r"(b0), "r"(b1));
}

__global__ void __launch_bounds__(256, 2)
mix_kernel(const float* __restrict__ src, float* __restrict__ out) {
    extern __shared__ float smem[];
    float*    sS  = smem;                               // [64][260]
    uint32_t* sAh = (uint32_t*)(smem + TT * SS_STRIDE); // [64][36]
    uint32_t* sAl = sAh + TT * SA_STRIDE;

    const int b    = blockIdx.y;
    const int tid  = threadIdx.x;
    const int warp = tid >> 5, lane = tid & 31;
    const int colbase = blockIdx.x * 256;

    const uint32_t sS_a  = (uint32_t)__cvta_generic_to_shared(sS);
    const uint32_t sAh_a = (uint32_t)__cvta_generic_to_shared(sAh);
    const uint32_t sAl_a = (uint32_t)__cvta_generic_to_shared(sAl);

    // --- async A tiles (pre-packed by softmax): 2 x 8KB contiguous ---
    const uint32_t* gAh = g_Ah + b * 2048;
    const uint32_t* gAl = g_Al + b * 2048;
    #pragma unroll
    for (int j = 0; j < 2; ++j) {
        const int k  = j * 256 + tid;
        const int a  = k >> 3, tp0 = (k & 7) * 4;
        cp_async16(sAh_a + (a * SA_STRIDE + tp0) * 4, gAh + a * 32 + tp0);
        cp_async16(sAl_a + (a * SA_STRIDE + tp0) * 4, gAl + a * 32 + tp0);
    }

    // --- async src tile: 64 x 256 fp32 (64 KB) ---
    const float* sb = src + (size_t)b * TT * ND + colbase;
    #pragma unroll
    for (int it = 0; it < 16; ++it) {
        const int i = it * 256 + tid;
        const int t = i >> 6, c4 = i & 63;
        cp_async16(sS_a + (t * SS_STRIDE + c4 * 4) * 4, sb + (size_t)t * ND + c4 * 4);
    }
    asm volatile("cp.async.commit_group;");
    asm volatile("cp.async.wait_group 0;");
    __syncthreads();

    const int g   = lane >> 2;
    const int tg  = lane & 3;
    const int n0w = warp * 32;

    float acc[4][4][4];
    #pragma unroll
    for (int mt = 0; mt < 4; ++mt)
        #pragma unroll
        for (int nt = 0; nt < 4; ++nt)
            #pragma unroll
            for (int f = 0; f < 4; ++f) acc[mt][nt][f] = 0.f;

    #pragma unroll
    for (int ks = 0; ks < 4; ++ks) {
        // --- stage B fragments for all 4 nt (16 regs) ---
        uint32_t Bh0[4], Bh1[4], Bl0[4], Bl1[4];
        #pragma unroll
        for (int nt = 0; nt < 4; ++nt) {
            const int c  = n0w + nt * 8 + g;
            const int t0 = ks * 16 + 2 * tg;
            const float v0 = sS[(t0)     * SS_STRIDE + c];
            const float v1 = sS[(t0 + 1) * SS_STRIDE + c];
            const float v2 = sS[(t0 + 8) * SS_STRIDE + c];
            const float v3 = sS[(t0 + 9) * SS_STRIDE + c];
            const float h0 = bf16_round(v0), h1 = bf16_round(v1);
            const float h2 = bf16_round(v2), h3 = bf16_round(v3);
            Bh0[nt] = pack_bf16x2(h0, h1);
            Bh1[nt] = pack_bf16x2(h2, h3);
            Bl0[nt] = pack_bf16x2(v0 - h0, v1 - h1);
            Bl1[nt] = pack_bf16x2(v2 - h2, v3 - h3);
        }
        // --- per-mt: load A just-in-time (8 regs), fire 12 MMAs ---
        #pragma unroll
        for (int mt = 0; mt < 4; ++mt) {
            const int r0 = (mt * 16 + g) * SA_STRIDE + ks * 8 + tg;
            const int r1 = r0 + 8 * SA_STRIDE;
            const uint32_t ah0 = sAh[r0],     ah1 = sAh[r1];
            const uint32_t ah2 = sAh[r0 + 4], ah3 = sAh[r1 + 4];
            const uint32_t al0 = sAl[r0],     al1 = sAl[r1];
            const uint32_t al2 = sAl[r0 + 4], al3 = sAl[r1 + 4];
            #pragma unroll
            for (int nt = 0; nt < 4; ++nt) {
                mma_bf16(acc[mt][nt], ah0, ah1, ah2, ah3, Bh0[nt], Bh1[nt]);
                mma_bf16(acc[mt][nt], al0, al1, al2, al3, Bh0[nt], Bh1[nt]);
                mma_bf16(acc[mt][nt], ah0, ah1, ah2, ah3, Bl0[nt], Bl1[nt]);
            }
        }
    }

    // --- epilogue: out = mixed + src (fp32 residual from smem tile) ---
    float* ob = out + (size_t)b * TT * ND + colbase;
    #pragma unroll
    for (int mt = 0; mt < 4; ++mt) {
        const int a0 = mt * 16 + g;
        #pragma unroll
        for (int nt = 0; nt < 4; ++nt) {
            const int c = n0w + nt * 8 + 2 * tg;
            float2 v0, v1;
            v0.x = acc[mt][nt][0] + sS[a0 * SS_STRIDE + c];
            v0.y = acc[mt][nt][1] + sS[a0 * SS_STRIDE + c + 1];
            v1.x = acc[mt][nt][2] + sS[(a0 + 8) * SS_STRIDE + c];
            v1.y = acc[mt][nt][3] + sS[(a0 + 8) * SS_STRIDE + c + 1];
            *reinterpret_cast<float2*>(ob + (size_t)a0       * ND + c) = v0;
            *reinterpret_cast<float2*>(ob + (size_t)(a0 + 8) * ND + c) = v1;
        }
    }
}

// ---------------------------------------------------------------------------
extern "C" void kernel_launch(void* const* d_in, const int* in_sizes, int n_in,
                              void* d_out, int out_size) {
    const float *src = nullptr, *wt1 = nullptr, *wt2 = nullptr, *wt3 = nullptr;
    for (int i = 0; i < n_in; ++i) {
        const int s = in_sizes[i];
        if      (s == BB * TT * NN * DD) src = (const float*)d_in[i];
        else if (s == DD)                wt1 = (const float*)d_in[i];
        else if (s == NN * DD)           wt2 = (const float*)d_in[i];
        else if (s == NN)                wt3 = (const float*)d_in[i];
    }
    float* out = (float*)d_out;

    static bool attr_done = false;
    if (!attr_done) {
        cudaFuncSetAttribute(mix_kernel,
                             cudaFuncAttributeMaxDynamicSharedMemorySize,
                             MIX_SMEM_BYTES);
        attr_done = true;
    }

    qk_kernel<<<BT, 256>>>(src, wt1, wt3);
    mscores_kernel<<<dim3(BB, 8), 256>>>(wt2);
    softmax_kernel<<<256, 256>>>();
    mix_kernel<<<dim3(ND / 256, BB), 256, MIX_SMEM_BYTES>>>(src, out);
}

// round 13
// speedup vs baseline: 1.0097x; 1.0097x over previous
#include <cuda_runtime.h>
#include <cuda_bf16.h>
#include <cstring>
#include <cstdint>

// Shapes
#define BB 32
#define TT 64
#define NN 300
#define DD 128
#define ND (NN*DD)          // 38400
#define BT (BB*TT)          // 2048

#define SA_STRIDE 36        // A row stride (uint32), padded, conflict-free
#define A_WORDS (TT*SA_STRIDE)   // 2304 u32 = 9216 B per batch per array

// Scratch (static __device__ — no allocation allowed)
__device__ float    g_Q[BB*TT*NN];      // [b,t,n]
__device__ float    g_K[BB*TT*DD];      // [b,t,d]
__device__ float    g_S[BB*TT*TT];      // scores [b,q,k]
__device__ uint32_t g_Ah[BB*A_WORDS];   // att^T bf16x2 hi, PRE-PADDED stride 36
__device__ uint32_t g_Al[BB*A_WORDS];   // att^T bf16x2 lo, PRE-PADDED stride 36

__device__ __forceinline__ float bf16_round(float v) {
    return __bfloat162float(__float2bfloat16_rn(v));
}
// pack two floats as bf16x2; 'lo' goes to bits [15:0] (lower k index)
__device__ __forceinline__ uint32_t pack_bf16x2(float lo, float hi) {
    uint32_t r;
    asm("cvt.rn.bf16x2.f32 %0, %1, %2;" : "=r"(r) : "f"(hi), "f"(lo));
    return r;
}

// ---- bulk-copy / mbarrier primitives ----
__device__ __forceinline__ void bulk_ld(uint32_t dst_smem, const void* src,
                                        uint32_t bytes, uint32_t mbar) {
    asm volatile(
        "cp.async.bulk.shared::cluster.global.mbarrier::complete_tx::bytes "
        "[%0], [%1], %2, [%3];"
        :: "r"(dst_smem), "l"(src), "r"(bytes), "r"(mbar) : "memory");
}
__device__ __forceinline__ void bulk_st(void* dst, uint32_t src_smem, uint32_t bytes) {
    asm volatile(
        "cp.async.bulk.global.shared::cta.bulk_group [%0], [%1], %2;"
        :: "l"(dst), "r"(src_smem), "r"(bytes) : "memory");
}
__device__ __forceinline__ void mbar_init(uint32_t mbar, uint32_t count) {
    asm volatile("mbarrier.init.shared.b64 [%0], %1;" :: "r"(mbar), "r"(count) : "memory");
}
__device__ __forceinline__ void mbar_expect_tx(uint32_t mbar, uint32_t bytes) {
    asm volatile("mbarrier.arrive.expect_tx.shared.b64 _, [%0], %1;"
                 :: "r"(mbar), "r"(bytes) : "memory");
}
__device__ __forceinline__ void mbar_wait(uint32_t mbar, uint32_t parity) {
    uint32_t done = 0;
    while (!done) {
        asm volatile(
            "{\n\t.reg .pred p;\n\t"
            "mbarrier.try_wait.parity.shared::cta.b64 p, [%1], %2;\n\t"
            "selp.b32 %0, 1, 0, p;\n\t}"
            : "=r"(done) : "r"(mbar), "r"(parity) : "memory");
    }
}

// ---------------------------------------------------------------------------
// Kernel 1 (FUSED, single pass over src):
//   Q[bt,n] = dot(src[bt,n,:], wt1);  K[bt,d] = sum_n wt3[n]*src[bt,n,d]
// ---------------------------------------------------------------------------
#define SP_STRIDE 33

__global__ void __launch_bounds__(256)
qk_kernel(const float* __restrict__ src,
          const float* __restrict__ wt1,
          const float* __restrict__ wt3) {
    const int bt  = blockIdx.x;
    const int tid = threadIdx.x;
    const float* base = src + (size_t)bt * ND;

    __shared__ float  sw3[NN];
    __shared__ float  sP[NN * SP_STRIDE];
    __shared__ float4 sKred[8][32];

    for (int i = tid; i < NN; i += 256) sw3[i] = wt3[i];
    __syncthreads();

    const int warp = tid >> 5, lane = tid & 31;
    const float4 w1v = reinterpret_cast<const float4*>(wt1)[lane];
    float4 kacc = make_float4(0.f, 0.f, 0.f, 0.f);

    #pragma unroll 8
    for (int n = warp; n < NN; n += 8) {
        const float4 v = reinterpret_cast<const float4*>(base + n * DD)[lane];
        const float w3n = sw3[n];
        kacc.x += w3n * v.x; kacc.y += w3n * v.y;
        kacc.z += w3n * v.z; kacc.w += w3n * v.w;
        sP[n * SP_STRIDE + lane] =
            v.x * w1v.x + v.y * w1v.y + v.z * w1v.z + v.w * w1v.w;
    }

    sKred[warp][lane] = kacc;
    __syncthreads();

    for (int n = tid; n < NN; n += 256) {
        const float* row = sP + n * SP_STRIDE;
        float s = 0.f;
        #pragma unroll
        for (int j = 0; j < 32; ++j) s += row[j];
        g_Q[bt * NN + n] = s;
    }

    if (tid < 128) {
        const int l = tid >> 2, comp = tid & 3;
        float s = 0.f;
        #pragma unroll
        for (int w = 0; w < 8; ++w)
            s += reinterpret_cast<const float*>(&sKred[w][l])[comp];
        g_K[bt * DD + tid] = s;
    }
}

// ---------------------------------------------------------------------------
// Kernel 2 (FUSED m+scores): per (b, 8-q tile) — 256 CTAs, warp = 1 q row.
// ---------------------------------------------------------------------------
__global__ void __launch_bounds__(256)
mscores_kernel(const float* __restrict__ wt2) {
    const int b = blockIdx.x, qt = blockIdx.y;
    const int tid = threadIdx.x;
    const int warp = tid >> 5, lane = tid & 31;

    __shared__ float sQ[8 * NN];
    __shared__ float sM[8 * DD];
    __shared__ float sK[TT * 129];

    for (int i = tid; i < 8 * NN; i += 256)
        sQ[i] = g_Q[(b * TT + qt * 8) * NN + i];
    for (int i = tid; i < TT * DD; i += 256) {
        const int k = i >> 7, d = i & 127;
        sK[k * 129 + d] = g_K[(b * TT + k) * DD + d];
    }
    __syncthreads();

    {
        const int q = warp;
        float acc[4] = {0.f, 0.f, 0.f, 0.f};
        #pragma unroll 4
        for (int n = 0; n < NN; ++n) {
            const float qv = sQ[q * NN + n];
            const float* w2 = wt2 + n * DD;
            #pragma unroll
            for (int j = 0; j < 4; ++j)
                acc[j] += qv * w2[lane + 32 * j];
        }
        #pragma unroll
        for (int j = 0; j < 4; ++j)
            sM[q * DD + lane + 32 * j] = acc[j];
    }
    __syncthreads();

    #pragma unroll
    for (int pi = 0; pi < 2; ++pi) {
        const int p = pi * 256 + tid;
        const int q = p >> 6, k = p & 63;
        float acc = 0.f;
        #pragma unroll 8
        for (int d = 0; d < DD; ++d)
            acc += sM[q * DD + d] * sK[k * 129 + d];
        g_S[(b * TT + qt * 8 + q) * TT + k] = acc;
    }
}

// ---------------------------------------------------------------------------
// Kernel 3: softmax over BATCH axis + transpose + bf16 hi/lo pre-pack,
// written PRE-PADDED (stride 36) so mix can bulk-copy A contiguously.
// ---------------------------------------------------------------------------
__global__ void __launch_bounds__(256)
softmax_kernel() {
    const int warp = threadIdx.x >> 5, lane = threadIdx.x & 31;
    const int w  = blockIdx.x * 8 + warp;
    const int a  = w >> 5, tp = w & 31;

    const float x0 = g_S[lane * (TT * TT) + (2 * tp) * TT + a];
    const float x1 = g_S[lane * (TT * TT) + (2 * tp + 1) * TT + a];
    float m0 = x0, m1 = x1;
    #pragma unroll
    for (int off = 16; off > 0; off >>= 1) {
        m0 = fmaxf(m0, __shfl_xor_sync(0xffffffffu, m0, off));
        m1 = fmaxf(m1, __shfl_xor_sync(0xffffffffu, m1, off));
    }
    const float e0 = __expf(x0 - m0), e1 = __expf(x1 - m1);
    float s0 = e0, s1 = e1;
    #pragma unroll
    for (int off = 16; off > 0; off >>= 1) {
        s0 += __shfl_xor_sync(0xffffffffu, s0, off);
        s1 += __shfl_xor_sync(0xffffffffu, s1, off);
    }
    const float v0 = e0 / s0, v1 = e1 / s1;
    const float h0 = bf16_round(v0), h1 = bf16_round(v1);
    const int idx = a * SA_STRIDE + tp;
    g_Ah[lane * A_WORDS + idx] = pack_bf16x2(h0, h1);
    g_Al[lane * A_WORDS + idx] = pack_bf16x2(v0 - h0, v1 - h1);
}

// ---------------------------------------------------------------------------
// Kernel 4 (TENSOR): mixed[a,c] = sum_t att^T[a,t]*src[t,c]; out = mixed+src.
// bf16-split MMA; 64x256 tile; 2 CTAs/SM.  NEW: all bulk traffic moved to the
// TMA/bulk engine — 66 cp.async.bulk loads on an mbarrier, epilogue staged in
// smem and written with 64 cp.async.bulk stores. l1tex left to fragment LDS.
// ---------------------------------------------------------------------------
#define SS_STRIDE 260   // floats; row pitch 1040 B (16B-aligned); conflict-free
// bytes: sS 66560 + sAh 9216 + sAl 9216 + mbar 16 = 85008
#define MIX_SMEM_BYTES 85008
#define TOTAL_TX (TT*1024 + 2*9216)   // 83968

__device__ __forceinline__ void mma_bf16(float c[4],
                                         uint32_t a0, uint32_t a1,
                                         uint32_t a2, uint32_t a3,
                                         uint32_t b0, uint32_t b1) {
    asm volatile(
        "mma.sync.aligned.m16n8k16.row.col.f32.bf16.bf16.f32 "
        "{%0,%1,%2,%3}, {%4,%5,%6,%7}, {%8,%9}, {%0,%1,%2,%3};"
        : "+f"(c[0]), "+f"(c[1]), "+f"(c[2]), "+f"(c[3])
        : "r"(a0), "r"(a1), "r"(a2), "r"(a3), "r"(b0), "r"(b1));
}

__global__ void __launch_bounds__(256, 2)
mix_kernel(const float* __restrict__ src, float* __restrict__ out) {
    extern __shared__ float smem[];
    float*    sS  = smem;                               // [64][260]
    uint32_t* sAh = (uint32_t*)(smem + TT * SS_STRIDE); // [64][36] padded
    uint32_t* sAl = sAh + A_WORDS;
    uint64_t* mb  = (uint64_t*)(sAl + A_WORDS);

    const int b    = blockIdx.y;
    const int tid  = threadIdx.x;
    const int warp = tid >> 5, lane = tid & 31;
    const int colbase = blockIdx.x * 256;

    const uint32_t sS_a  = (uint32_t)__cvta_generic_to_shared(sS);
    const uint32_t sAh_a = (uint32_t)__cvta_generic_to_shared(sAh);
    const uint32_t sAl_a = (uint32_t)__cvta_generic_to_shared(sAl);
    const uint32_t mb_a  = (uint32_t)__cvta_generic_to_shared(mb);

    const float* sb = src + (size_t)b * TT * ND + colbase;

    // --- mbarrier setup + bulk loads ---
    if (tid == 0) mbar_init(mb_a, 1);
    __syncthreads();
    if (tid == 0) mbar_expect_tx(mb_a, TOTAL_TX);
    __syncthreads();
    if (tid < TT) {
        bulk_ld(sS_a + tid * (SS_STRIDE * 4), sb + (size_t)tid * ND, 1024, mb_a);
    } else if (tid == 64) {
        bulk_ld(sAh_a, g_Ah + b * A_WORDS, 9216, mb_a);
    } else if (tid == 65) {
        bulk_ld(sAl_a, g_Al + b * A_WORDS, 9216, mb_a);
    }
    mbar_wait(mb_a, 0);

    const int g   = lane >> 2;
    const int tg  = lane & 3;
    const int n0w = warp * 32;

    float acc[4][4][4];
    #pragma unroll
    for (int mt = 0; mt < 4; ++mt)
        #pragma unroll
        for (int nt = 0; nt < 4; ++nt)
            #pragma unroll
            for (int f = 0; f < 4; ++f) acc[mt][nt][f] = 0.f;

    #pragma unroll
    for (int ks = 0; ks < 4; ++ks) {
        // --- stage B fragments for all 4 nt (16 regs) ---
        uint32_t Bh0[4], Bh1[4], Bl0[4], Bl1[4];
        #pragma unroll
        for (int nt = 0; nt < 4; ++nt) {
            const int c  = n0w + nt * 8 + g;
            const int t0 = ks * 16 + 2 * tg;
            const float v0 = sS[(t0)     * SS_STRIDE + c];
            const float v1 = sS[(t0 + 1) * SS_STRIDE + c];
            const float v2 = sS[(t0 + 8) * SS_STRIDE + c];
            const float v3 = sS[(t0 + 9) * SS_STRIDE + c];
            const float h0 = bf16_round(v0), h1 = bf16_round(v1);
            const float h2 = bf16_round(v2), h3 = bf16_round(v3);
            Bh0[nt] = pack_bf16x2(h0, h1);
            Bh1[nt] = pack_bf16x2(h2, h3);
            Bl0[nt] = pack_bf16x2(v0 - h0, v1 - h1);
            Bl1[nt] = pack_bf16x2(v2 - h2, v3 - h3);
        }
        // --- per-mt: load A just-in-time (8 regs), fire 12 MMAs ---
        #pragma unroll
        for (int mt = 0; mt < 4; ++mt) {
            const int r0 = (mt * 16 + g) * SA_STRIDE + ks * 8 + tg;
            const int r1 = r0 + 8 * SA_STRIDE;
            const uint32_t ah0 = sAh[r0],     ah1 = sAh[r1];
            const uint32_t ah2 = sAh[r0 + 4], ah3 = sAh[r1 + 4];
            const uint32_t al0 = sAl[r0],     al1 = sAl[r1];
            const uint32_t al2 = sAl[r0 + 4], al3 = sAl[r1 + 4];
            #pragma unroll
            for (int nt = 0; nt < 4; ++nt) {
                mma_bf16(acc[mt][nt], ah0, ah1, ah2, ah3, Bh0[nt], Bh1[nt]);
                mma_bf16(acc[mt][nt], al0, al1, al2, al3, Bh0[nt], Bh1[nt]);
                mma_bf16(acc[mt][nt], ah0, ah1, ah2, ah3, Bl0[nt], Bl1[nt]);
            }
        }
    }

    // --- epilogue: add fp32 residual from sS, then stage into sS + bulk store ---
    #pragma unroll
    for (int mt = 0; mt < 4; ++mt) {
        const int a0 = mt * 16 + g;
        #pragma unroll
        for (int nt = 0; nt < 4; ++nt) {
            const int c = n0w + nt * 8 + 2 * tg;
            const float2 r0 = *reinterpret_cast<const float2*>(sS + a0 * SS_STRIDE + c);
            const float2 r1 = *reinterpret_cast<const float2*>(sS + (a0 + 8) * SS_STRIDE + c);
            acc[mt][nt][0] += r0.x; acc[mt][nt][1] += r0.y;
            acc[mt][nt][2] += r1.x; acc[mt][nt][3] += r1.y;
        }
    }
    __syncthreads();
    #pragma unroll
    for (int mt = 0; mt < 4; ++mt) {
        const int a0 = mt * 16 + g;
        #pragma unroll
        for (int nt = 0; nt < 4; ++nt) {
            const int c = n0w + nt * 8 + 2 * tg;
            *reinterpret_cast<float2*>(sS + a0 * SS_STRIDE + c) =
                make_float2(acc[mt][nt][0], acc[mt][nt][1]);
            *reinterpret_cast<float2*>(sS + (a0 + 8) * SS_STRIDE + c) =
                make_float2(acc[mt][nt][2], acc[mt][nt][3]);
        }
    }
    __syncthreads();

    float* ob = out + (size_t)b * TT * ND + colbase;
    if (tid < TT) {
        asm volatile("fence.proxy.async;" ::: "memory");
        bulk_st(ob + (size_t)tid * ND, sS_a + tid * (SS_STRIDE * 4), 1024);
        asm volatile("cp.async.bulk.commit_group;" ::: "memory");
        asm volatile("cp.async.bulk.wait_group.read 0;" ::: "memory");
    }
}

// ---------------------------------------------------------------------------
extern "C" void kernel_launch(void* const* d_in, const int* in_sizes, int n_in,
                              void* d_out, int out_size) {
    const float *src = nullptr, *wt1 = nullptr, *wt2 = nullptr, *wt3 = nullptr;
    for (int i = 0; i < n_in; ++i) {
        const int s = in_sizes[i];
        if      (s == BB * TT * NN * DD) src = (const float*)d_in[i];
        else if (s == DD)                wt1 = (const float*)d_in[i];
        else if (s == NN * DD)           wt2 = (const float*)d_in[i];
        else if (s == NN)                wt3 = (const float*)d_in[i];
    }
    float* out = (float*)d_out;

    static bool attr_done = false;
    if (!attr_done) {
        cudaFuncSetAttribute(mix_kernel,
                             cudaFuncAttributeMaxDynamicSharedMemorySize,
                             MIX_SMEM_BYTES);
        attr_done = true;
    }

    qk_kernel<<<BT, 256>>>(src, wt1, wt3);
    mscores_kernel<<<dim3(BB, 8), 256>>>(wt2);
    softmax_kernel<<<256, 256>>>();
    mix_kernel<<<dim3(ND / 256, BB), 256, MIX_SMEM_BYTES>>>(src, out);
}